// round 10
// baseline (speedup 1.0000x reference)
#include <cuda_runtime.h>
#include <cuda_bf16.h>
#include <math.h>
#include <stdint.h>

typedef __nv_bfloat16 bf16;

// Problem constants
#define B_   4
#define E_   32
#define D_   1024
#define NH_  16
#define NP_  4
#define LQ_  1024          // E*E
#define DH_  64            // D/NH

// ---------------------------------------------------------------------------
// Scratch (static device globals; allocation APIs are forbidden)
// ---------------------------------------------------------------------------
__device__ bf16  g_fn    [B_ * 4 * LQ_ * D_];   // 32 MB  LN(concat srcs), bf16
__device__ bf16  g_qn    [B_ * LQ_ * D_];       //  8 MB  LN(src3), bf16
__device__ bf16  g_val   [B_ * 4 * LQ_ * D_];   // 32 MB  CA value (bf16)
__device__ float g_offaw [B_ * LQ_ * 768];      // 12 MB  CA off(512)+aw(256)
__device__ bf16  g_samp  [B_ * LQ_ * D_];       //  8 MB  CA sampled, bf16
__device__ float g_attn  [B_ * LQ_ * D_];       // 16 MB
__device__ bf16  g_attn1 [B_ * LQ_ * D_];       //  8 MB  LN(attn), bf16
__device__ bf16  g_val2  [B_ * LQ_ * D_];       //  8 MB  SA value (bf16)
__device__ float g_offaw2[B_ * LQ_ * 192];      //  3 MB  SA off(128)+aw(64)
__device__ bf16  g_samp2 [B_ * LQ_ * D_];       //  8 MB  bf16
__device__ float g_attn2 [B_ * LQ_ * D_];       // 16 MB
__device__ bf16  g_wrb   [5177344];             // 10.4 MB bf16 weights

// Weight segment offsets (elements) inside g_wrb
#define WOFF_CAVW 0
#define WOFF_CAOW 1048576
#define WOFF_CAAW 1572864
#define WOFF_CAPW 1835008
#define WOFF_SAVW 2883584
#define WOFF_SAOW 3932160
#define WOFF_SAAW 4063232
#define WOFF_SAPW 4128768
#define WTOT      5177344

// ---------------------------------------------------------------------------
// Helpers
// ---------------------------------------------------------------------------
__device__ __forceinline__ uint32_t smem_u32(const void* p) {
    uint32_t a;
    asm("{ .reg .u64 t; cvta.to.shared.u64 t, %1; cvt.u32.u64 %0, t; }"
        : "=r"(a) : "l"(p));
    return a;
}
__device__ __forceinline__ void cp16(uint32_t s, const void* g) {
    asm volatile("cp.async.cg.shared.global [%0], [%1], 16;\n" :: "r"(s), "l"(g));
}
__device__ __forceinline__ void cp16p(uint32_t s, const void* g, uint32_t nbytes) {
    asm volatile("cp.async.cg.shared.global [%0], [%1], 16, %2;\n"
                 :: "r"(s), "l"(g), "r"(nbytes));
}
__device__ __forceinline__ void ldsm4(uint32_t* r, uint32_t a) {
    asm volatile("ldmatrix.sync.aligned.m8n8.x4.shared.b16 {%0,%1,%2,%3}, [%4];"
                 : "=r"(r[0]), "=r"(r[1]), "=r"(r[2]), "=r"(r[3]) : "r"(a));
}
__device__ __forceinline__ void mma_bf16(float* d, const uint32_t* a,
                                         uint32_t b0, uint32_t b1) {
    asm volatile(
        "mma.sync.aligned.m16n8k16.row.col.f32.bf16.bf16.f32 "
        "{%0,%1,%2,%3}, {%4,%5,%6,%7}, {%8,%9}, {%0,%1,%2,%3};"
        : "+f"(d[0]), "+f"(d[1]), "+f"(d[2]), "+f"(d[3])
        : "r"(a[0]), "r"(a[1]), "r"(a[2]), "r"(a[3]), "r"(b0), "r"(b1));
}
__device__ __forceinline__ uint32_t pack_bf16(float lo, float hi) {
    __nv_bfloat162 p = __floats2bfloat162_rn(lo, hi);
    return *reinterpret_cast<uint32_t*>(&p);
}

// ---------------------------------------------------------------------------
// BF16 tensor-core GEMM:  C(M,N) = A(M,K=1024) @ W(N,K=1024)^T + bias(N)
// Block 128x128x32, 256 threads / 8 warps (each warp 32x64), 3-stage cp.async.
// A/W bf16, accum fp32; OutT selects fp32 or bf16 (packed) C stores.
// Fragments via ldmatrix.x4; 80B smem row stride (16B-aligned, conflict-free).
// Split-bias epilogue supports fused GEMMs: col < split -> bias1, else bias2.
// ---------------------------------------------------------------------------
#define RSTR 80              // bytes per smem row
#define STGB (128 * RSTR)    // bytes per matrix per stage (10240)
#define NSTAGE 3

template<typename OutT>
__global__ void __launch_bounds__(256, 2) gemm_bf16(
    const bf16* __restrict__ A, const bf16* __restrict__ W,
    const float* __restrict__ bias1, const float* __restrict__ bias2,
    int split, OutT* __restrict__ C, int N)
{
    extern __shared__ char smraw[];
    uint32_t abase = smem_u32(smraw);
    uint32_t bbase = abase + NSTAGE * STGB;

    const int K = 1024, NIT = 32;
    int tid = threadIdx.x, wid = tid >> 5, lane = tid & 31;
    int wm = wid & 3, wn = wid >> 2;          // warp tile: rows wm*32, cols wn*64
    int bm = blockIdx.y * 128, bn = blockIdx.x * 128;

    float acc[2][8][4];
    #pragma unroll
    for (int mt = 0; mt < 2; mt++)
        #pragma unroll
        for (int nt = 0; nt < 8; nt++)
            #pragma unroll
            for (int i = 0; i < 4; i++) acc[mt][nt][i] = 0.f;

    int rowC = tid >> 2, jc = tid & 3;   // 256 threads: 64 rows x 4 chunks / pass

    auto load_stage = [&](int s, int it) {
        int k0 = it * 32;                // bf16 element offset in K
        #pragma unroll
        for (int i = 0; i < 2; ++i) {
            int row = rowC + i * 64;
            cp16(abase + s * STGB + row * RSTR + jc * 16,
                 A + (size_t)(bm + row) * K + k0 + jc * 8);
            int srow = bn + row;
            const bf16* src = W + (size_t)(srow < N ? srow : 0) * K + k0 + jc * 8;
            cp16p(bbase + s * STGB + row * RSTR + jc * 16,
                  src, srow < N ? 16u : 0u);
        }
        asm volatile("cp.async.commit_group;" ::: "memory");
    };

    // Per-thread ldmatrix row addresses.
    int rA = lane & 15, hA = lane >> 4;
    uint32_t aAddr = abase + (uint32_t)(wm * 32 + rA) * RSTR + hA * 16;
    int rB = (lane & 7) | ((lane >> 4) << 3);
    int hB = (lane >> 3) & 1;
    uint32_t bAddr = bbase + (uint32_t)(wn * 64 + rB) * RSTR + hB * 16;

    load_stage(0, 0);
    load_stage(1, 1);

    int s = 0, pf = 2;
    for (int it = 0; it < NIT; ++it) {
        asm volatile("cp.async.wait_group 1;" ::: "memory");
        __syncthreads();
        if (it + 2 < NIT) {
            load_stage(pf, it + 2);
            pf = (pf == NSTAGE - 1) ? 0 : pf + 1;
        }

        uint32_t ao = aAddr + s * STGB;
        uint32_t bo = bAddr + s * STGB;
        #pragma unroll
        for (int ks = 0; ks < 2; ks++) {          // two k16 steps per BK=32
            uint32_t af[2][4];
            #pragma unroll
            for (int mt = 0; mt < 2; mt++)
                ldsm4(af[mt], ao + mt * (16 * RSTR) + ks * 32);
            #pragma unroll
            for (int nb = 0; nb < 4; nb++) {
                uint32_t bb4[4];
                ldsm4(bb4, bo + nb * (16 * RSTR) + ks * 32);
                #pragma unroll
                for (int mt = 0; mt < 2; mt++) {
                    mma_bf16(acc[mt][2 * nb],     af[mt], bb4[0], bb4[1]);
                    mma_bf16(acc[mt][2 * nb + 1], af[mt], bb4[2], bb4[3]);
                }
            }
        }
        s = (s == NSTAGE - 1) ? 0 : s + 1;
    }

    // Epilogue (split-bias for fused GEMMs)
    int g = lane >> 2, c = lane & 3;
    #pragma unroll
    for (int mt = 0; mt < 2; mt++) {
        int r0 = bm + wm * 32 + mt * 16 + g;
        #pragma unroll
        for (int nt = 0; nt < 8; nt++) {
            int colb = bn + wn * 64 + nt * 8;
            if (colb < N) {
                int cg = colb + 2 * c;
                const float* bp = (colb < split) ? (bias1 + cg) : (bias2 + cg - split);
                float2 bv = *(const float2*)bp;
                float v00 = acc[mt][nt][0] + bv.x, v01 = acc[mt][nt][1] + bv.y;
                float v10 = acc[mt][nt][2] + bv.x, v11 = acc[mt][nt][3] + bv.y;
                if constexpr (sizeof(OutT) == 4) {
                    *(float2*)((float*)C + (size_t)r0 * N + cg) = make_float2(v00, v01);
                    *(float2*)((float*)C + (size_t)(r0 + 8) * N + cg) = make_float2(v10, v11);
                } else {
                    *(uint32_t*)((bf16*)C + (size_t)r0 * N + cg) = pack_bf16(v00, v01);
                    *(uint32_t*)((bf16*)C + (size_t)(r0 + 8) * N + cg) = pack_bf16(v10, v11);
                }
            }
        }
    }
}

// ---------------------------------------------------------------------------
// LayerNorm (one block per 1024-float row). fp32 in -> bf16 out.
// ---------------------------------------------------------------------------
__global__ void __launch_bounds__(256) ln_kernel(
    const float* __restrict__ in, const float* __restrict__ g,
    const float* __restrict__ b, bf16* __restrict__ out)
{
    __shared__ float red[16];
    int r = blockIdx.x;
    const float4* x4 = (const float4*)(in + (size_t)r * D_);

    int t = threadIdx.x;
    float4 v = x4[t];
    float s  = v.x + v.y + v.z + v.w;
    float ss = v.x * v.x + v.y * v.y + v.z * v.z + v.w * v.w;
    #pragma unroll
    for (int o = 16; o; o >>= 1) {
        s  += __shfl_xor_sync(0xFFFFFFFFu, s,  o);
        ss += __shfl_xor_sync(0xFFFFFFFFu, ss, o);
    }
    int warp = t >> 5, lane = t & 31;
    if (lane == 0) { red[warp] = s; red[8 + warp] = ss; }
    __syncthreads();
    if (t == 0) {
        float S = 0.f, SS = 0.f;
        #pragma unroll
        for (int i = 0; i < 8; i++) { S += red[i]; SS += red[8 + i]; }
        red[0] = S; red[8] = SS;
    }
    __syncthreads();
    float mean = red[0] * (1.0f / D_);
    float var  = red[8] * (1.0f / D_) - mean * mean;
    float inv  = rsqrtf(var + 1e-6f);

    float4 gg = ((const float4*)g)[t];
    float4 bv = ((const float4*)b)[t];
    uint2 u;
    u.x = pack_bf16((v.x - mean) * inv * gg.x + bv.x,
                    (v.y - mean) * inv * gg.y + bv.y);
    u.y = pack_bf16((v.z - mean) * inv * gg.z + bv.z,
                    (v.w - mean) * inv * gg.w + bv.w);
    ((uint2*)(out + (size_t)r * D_))[t] = u;
}

// Fused feat-LN: 4 srcs -> concat layout, bf16. grid = 16384.
__global__ void __launch_bounds__(256) ln_feat_kernel(
    const float* __restrict__ s0, const float* __restrict__ s1,
    const float* __restrict__ s2, const float* __restrict__ s3,
    const float* __restrict__ g, const float* __restrict__ b,
    bf16* __restrict__ out)
{
    __shared__ float red[16];
    int l = blockIdx.x >> 12;
    int r = blockIdx.x & 4095;
    const float* in = (l == 0) ? s0 : (l == 1) ? s1 : (l == 2) ? s2 : s3;
    int bb = r >> 10, rr = r & 1023;
    const float4* x4 = (const float4*)(in + (size_t)r * D_);
    bf16* orow = out + ((size_t)bb * 4096 + l * 1024 + rr) * D_;

    int t = threadIdx.x;
    float4 v = x4[t];
    float s  = v.x + v.y + v.z + v.w;
    float ss = v.x * v.x + v.y * v.y + v.z * v.z + v.w * v.w;
    #pragma unroll
    for (int o = 16; o; o >>= 1) {
        s  += __shfl_xor_sync(0xFFFFFFFFu, s,  o);
        ss += __shfl_xor_sync(0xFFFFFFFFu, ss, o);
    }
    int warp = t >> 5, lane = t & 31;
    if (lane == 0) { red[warp] = s; red[8 + warp] = ss; }
    __syncthreads();
    if (t == 0) {
        float S = 0.f, SS = 0.f;
        #pragma unroll
        for (int i = 0; i < 8; i++) { S += red[i]; SS += red[8 + i]; }
        red[0] = S; red[8] = SS;
    }
    __syncthreads();
    float mean = red[0] * (1.0f / D_);
    float var  = red[8] * (1.0f / D_) - mean * mean;
    float inv  = rsqrtf(var + 1e-6f);

    float4 gg = ((const float4*)g)[t];
    float4 bv = ((const float4*)b)[t];
    uint2 u;
    u.x = pack_bf16((v.x - mean) * inv * gg.x + bv.x,
                    (v.y - mean) * inv * gg.y + bv.y);
    u.y = pack_bf16((v.z - mean) * inv * gg.z + bv.z,
                    (v.w - mean) * inv * gg.w + bv.w);
    ((uint2*)orow)[t] = u;
}

// ---------------------------------------------------------------------------
// Convert all 8 weight matrices to bf16 into g_wrb (single launch).
// ---------------------------------------------------------------------------
struct WPtrs { const float4 *p0,*p1,*p2,*p3,*p4,*p5,*p6,*p7; };

__global__ void round_weights(WPtrs w, bf16* __restrict__ dst)
{
    int i = blockIdx.x * blockDim.x + threadIdx.x;   // float4 index
    if (i >= WTOT / 4) return;
    const float4* src; int base;
    if      (i < WOFF_CAOW/4) { src = w.p0; base = 0; }
    else if (i < WOFF_CAAW/4) { src = w.p1; base = WOFF_CAOW/4; }
    else if (i < WOFF_CAPW/4) { src = w.p2; base = WOFF_CAAW/4; }
    else if (i < WOFF_SAVW/4) { src = w.p3; base = WOFF_CAPW/4; }
    else if (i < WOFF_SAOW/4) { src = w.p4; base = WOFF_SAVW/4; }
    else if (i < WOFF_SAAW/4) { src = w.p5; base = WOFF_SAOW/4; }
    else if (i < WOFF_SAPW/4) { src = w.p6; base = WOFF_SAAW/4; }
    else                      { src = w.p7; base = WOFF_SAPW/4; }
    float4 v = src[i - base];
    uint2 u;
    u.x = pack_bf16(v.x, v.y);
    u.y = pack_bf16(v.z, v.w);
    ((uint2*)dst)[i] = u;
}

// ---------------------------------------------------------------------------
// Softmax over P entries per (b,q,h) inside a combined off+aw row.
// ---------------------------------------------------------------------------
__global__ void softmax_kernel(float* __restrict__ comb, int rstride, int aoff,
                               int P, int total)
{
    int i = blockIdx.x * blockDim.x + threadIdx.x;
    if (i >= total) return;
    float* p = comb + (size_t)(i >> 4) * rstride + aoff + (i & 15) * P;
    float m = -1e30f;
    for (int j = 0; j < P; j++) m = fmaxf(m, p[j]);
    float s = 0.f;
    for (int j = 0; j < P; j++) { float e = __expf(p[j] - m); p[j] = e; s += e; }
    float inv = 1.0f / s;
    for (int j = 0; j < P; j++) p[j] *= inv;
}

// ---------------------------------------------------------------------------
// Deformable sampling: 1 block per (b,q), 16 warps = heads.
// value is bf16: each corner = one 128B line per warp (lane reads 2 bf16).
// Output bf16 (feeds the projection GEMM).
// ---------------------------------------------------------------------------
template<int NL>
__global__ void __launch_bounds__(512) deform_sample(
    const bf16* __restrict__ value, const float* __restrict__ comb,
    int rstride, int aoff, bf16* __restrict__ out)
{
    int bq = blockIdx.x;
    int b = bq >> 10, q = bq & 1023;
    int h = threadIdx.x >> 5, lane = threadIdx.x & 31;

    float rx = ((q & 31) + 0.5f) * 0.03125f;
    float ry = ((q >> 5) + 0.5f) * 0.03125f;

    const float* offp = comb + (size_t)bq * rstride + h * (NL * NP_ * 2);
    const float* awp  = comb + (size_t)bq * rstride + aoff + h * (NL * NP_);
    const bf16* vbase = value + (size_t)b * (NL * 1024) * D_ + h * DH_;

    float2 acc = make_float2(0.f, 0.f);

    #pragma unroll
    for (int l = 0; l < NL; l++) {
        #pragma unroll
        for (int p = 0; p < NP_; p++) {
            int s = l * NP_ + p;
            float ox = offp[s * 2 + 0];
            float oy = offp[s * 2 + 1];
            float a  = awp[s];
            float x = (rx + ox * 0.03125f) * 32.0f - 0.5f;
            float y = (ry + oy * 0.03125f) * 32.0f - 0.5f;
            float x0f = floorf(x), y0f = floorf(y);
            float wx1 = x - x0f, wy1 = y - y0f;
            int x0 = (int)x0f, y0 = (int)y0f;
            #pragma unroll
            for (int dy = 0; dy < 2; dy++) {
                int yi = y0 + dy;
                if ((unsigned)yi >= 32u) continue;
                float wy = dy ? wy1 : (1.0f - wy1);
                #pragma unroll
                for (int dx = 0; dx < 2; dx++) {
                    int xi = x0 + dx;
                    if ((unsigned)xi >= 32u) continue;
                    float w = (dx ? wx1 : (1.0f - wx1)) * wy * a;
                    const uint32_t* vp = (const uint32_t*)(vbase +
                        ((size_t)l * 1024 + yi * 32 + xi) * D_);
                    uint32_t pv = vp[lane];
                    float2 v = __bfloat1622float2(*reinterpret_cast<__nv_bfloat162*>(&pv));
                    acc.x += v.x * w;
                    acc.y += v.y * w;
                }
            }
        }
    }
    uint32_t pv = pack_bf16(acc.x, acc.y);
    ((uint32_t*)(out + (size_t)bq * D_ + h * DH_))[lane] = pv;
}

// ---------------------------------------------------------------------------
// Final residual combine: out = src3 + g1*(attn + g2*attn2)
// ---------------------------------------------------------------------------
__global__ void final_kernel(
    const float* __restrict__ src3, const float* __restrict__ attn,
    const float* __restrict__ attn2, const float* __restrict__ g1,
    const float* __restrict__ g2, float* __restrict__ out, int n4)
{
    int i = blockIdx.x * blockDim.x + threadIdx.x;
    if (i >= n4) return;
    int d4 = i & (D_ / 4 - 1);
    float4 s = ((const float4*)src3)[i];
    float4 a = ((const float4*)attn)[i];
    float4 a2 = ((const float4*)attn2)[i];
    float4 G1 = ((const float4*)g1)[d4];
    float4 G2 = ((const float4*)g2)[d4];
    float4 o;
    o.x = s.x + G1.x * (a.x + G2.x * a2.x);
    o.y = s.y + G1.y * (a.y + G2.y * a2.y);
    o.z = s.z + G1.z * (a.z + G2.z * a2.z);
    o.w = s.w + G1.w * (a.w + G2.w * a2.w);
    ((float4*)out)[i] = o;
}

// ---------------------------------------------------------------------------
// Host launcher
// ---------------------------------------------------------------------------
extern "C" void kernel_launch(void* const* d_in, const int* in_sizes, int n_in,
                              void* d_out, int out_size)
{
    const float* src[4] = {(const float*)d_in[0], (const float*)d_in[1],
                           (const float*)d_in[2], (const float*)d_in[3]};
    const float* qn_g = (const float*)d_in[4];
    const float* qn_b = (const float*)d_in[5];
    const float* fn_g = (const float*)d_in[6];
    const float* fn_b = (const float*)d_in[7];
    const float* n1_g = (const float*)d_in[8];
    const float* n1_b = (const float*)d_in[9];
    const float* gamma1 = (const float*)d_in[10];
    const float* gamma2 = (const float*)d_in[11];
    const float* ca_vb = (const float*)d_in[13];
    const float* ca_ob = (const float*)d_in[15];
    const float* ca_ab = (const float*)d_in[17];
    const float* ca_pb = (const float*)d_in[19];
    const float* sa_vb = (const float*)d_in[21];
    const float* sa_ob = (const float*)d_in[23];
    const float* sa_ab = (const float*)d_in[25];
    const float* sa_pb = (const float*)d_in[27];

    bf16 *fn, *qn, *val, *samp, *attn1, *val2, *samp2, *wr;
    float *offaw, *attn, *offaw2, *attn2;
    cudaGetSymbolAddress((void**)&fn,     g_fn);
    cudaGetSymbolAddress((void**)&qn,     g_qn);
    cudaGetSymbolAddress((void**)&val,    g_val);
    cudaGetSymbolAddress((void**)&offaw,  g_offaw);
    cudaGetSymbolAddress((void**)&samp,   g_samp);
    cudaGetSymbolAddress((void**)&attn,   g_attn);
    cudaGetSymbolAddress((void**)&attn1,  g_attn1);
    cudaGetSymbolAddress((void**)&val2,   g_val2);
    cudaGetSymbolAddress((void**)&offaw2, g_offaw2);
    cudaGetSymbolAddress((void**)&samp2,  g_samp2);
    cudaGetSymbolAddress((void**)&attn2,  g_attn2);
    cudaGetSymbolAddress((void**)&wr,     g_wrb);

    const int ROWS = B_ * LQ_;                    // 4096
    const int SMEM = 2 * NSTAGE * STGB;           // 61440 bytes

    cudaFuncSetAttribute(gemm_bf16<float>, cudaFuncAttributeMaxDynamicSharedMemorySize, SMEM);
    cudaFuncSetAttribute(gemm_bf16<bf16>,  cudaFuncAttributeMaxDynamicSharedMemorySize, SMEM);

    WPtrs wp = { (const float4*)d_in[12], (const float4*)d_in[14],
                 (const float4*)d_in[16], (const float4*)d_in[18],
                 (const float4*)d_in[20], (const float4*)d_in[22],
                 (const float4*)d_in[24], (const float4*)d_in[26] };

    // 1-3) LayerNorms + weight conversion (all bf16 outputs)
    ln_feat_kernel<<<4 * ROWS, 256>>>(src[0], src[1], src[2], src[3], fn_g, fn_b, fn);
    ln_kernel<<<ROWS, 256>>>(src[3], qn_g, qn_b, qn);
    round_weights<<<(WTOT / 4 + 255) / 256, 256>>>(wp, wr);
    // 4) Fused CA off+aw GEMM (N=768, split 512)
    gemm_bf16<float><<<dim3(6, 32), 256, SMEM>>>(qn, wr + WOFF_CAOW, ca_ob, ca_ab, 512, offaw, 768);
    // 5) softmax on aw part
    softmax_kernel<<<(ROWS * NH_ + 255) / 256, 256>>>(offaw, 768, 512, 16, ROWS * NH_);
    // 6) CA value GEMM, bf16 output (the launch ncu -s 5 -c 1 captures)
    gemm_bf16<bf16><<<dim3(8, 128), 256, SMEM>>>(fn, wr + WOFF_CAVW, ca_vb, ca_vb, 1024, val, 1024);
    // 7-8) sample + project
    deform_sample<4><<<ROWS, 512>>>(val, offaw, 768, 512, samp);
    gemm_bf16<float><<<dim3(8, 32), 256, SMEM>>>(samp, wr + WOFF_CAPW, ca_pb, ca_pb, 1024, attn, 1024);
    // 9-14) SA branch
    ln_kernel<<<ROWS, 256>>>(attn, n1_g, n1_b, attn1);
    gemm_bf16<bf16><<<dim3(8, 32), 256, SMEM>>>(attn1, wr + WOFF_SAVW, sa_vb, sa_vb, 1024, val2, 1024);
    gemm_bf16<float><<<dim3(2, 32), 256, SMEM>>>(attn1, wr + WOFF_SAOW, sa_ob, sa_ab, 128, offaw2, 192);
    softmax_kernel<<<(ROWS * NH_ + 255) / 256, 256>>>(offaw2, 192, 128, 4, ROWS * NH_);
    deform_sample<1><<<ROWS, 512>>>(val2, offaw2, 192, 128, samp2);
    gemm_bf16<float><<<dim3(8, 32), 256, SMEM>>>(samp2, wr + WOFF_SAPW, sa_pb, sa_pb, 1024, attn2, 1024);
    // 15) Final combine
    final_kernel<<<(ROWS * D_ / 4 + 255) / 256, 256>>>(
        src[3], attn, attn2, gamma1, gamma2, (float*)d_out, ROWS * D_ / 4);
}

// round 11
// speedup vs baseline: 1.0556x; 1.0556x over previous
#include <cuda_runtime.h>
#include <cuda_bf16.h>
#include <math.h>
#include <stdint.h>

typedef __nv_bfloat16 bf16;

// Problem constants
#define B_   4
#define E_   32
#define D_   1024
#define NH_  16
#define NP_  4
#define LQ_  1024          // E*E
#define DH_  64            // D/NH

// ---------------------------------------------------------------------------
// Scratch (static device globals; allocation APIs are forbidden)
// ---------------------------------------------------------------------------
__device__ bf16  g_fn    [B_ * 4 * LQ_ * D_];   // 32 MB  LN(concat srcs), bf16
__device__ bf16  g_qn    [B_ * LQ_ * D_];       //  8 MB  LN(src3), bf16
__device__ bf16  g_val   [B_ * 4 * LQ_ * D_];   // 32 MB  CA value (bf16)
__device__ float g_offaw [B_ * LQ_ * 768];      // 12 MB  CA off(512)+aw(256)
__device__ bf16  g_samp  [B_ * LQ_ * D_];       //  8 MB  CA sampled, bf16
__device__ float g_attn  [B_ * LQ_ * D_];       // 16 MB
__device__ bf16  g_attn1 [B_ * LQ_ * D_];       //  8 MB  LN(attn), bf16
__device__ bf16  g_val2  [B_ * LQ_ * D_];       //  8 MB  SA value (bf16)
__device__ float g_offaw2[B_ * LQ_ * 192];      //  3 MB  SA off(128)+aw(64)
__device__ bf16  g_samp2 [B_ * LQ_ * D_];       //  8 MB  bf16
__device__ float g_attn2 [B_ * LQ_ * D_];       // 16 MB
__device__ bf16  g_wrb   [5177344];             // 10.4 MB bf16 weights

// Weight segment offsets (elements) inside g_wrb
#define WOFF_CAVW 0
#define WOFF_CAOW 1048576
#define WOFF_CAAW 1572864
#define WOFF_CAPW 1835008
#define WOFF_SAVW 2883584
#define WOFF_SAOW 3932160
#define WOFF_SAAW 4063232
#define WOFF_SAPW 4128768
#define WTOT      5177344

// ---------------------------------------------------------------------------
// Helpers
// ---------------------------------------------------------------------------
__device__ __forceinline__ uint32_t smem_u32(const void* p) {
    uint32_t a;
    asm("{ .reg .u64 t; cvta.to.shared.u64 t, %1; cvt.u32.u64 %0, t; }"
        : "=r"(a) : "l"(p));
    return a;
}
__device__ __forceinline__ void cp16(uint32_t s, const void* g) {
    asm volatile("cp.async.cg.shared.global [%0], [%1], 16;\n" :: "r"(s), "l"(g));
}
__device__ __forceinline__ void cp16p(uint32_t s, const void* g, uint32_t nbytes) {
    asm volatile("cp.async.cg.shared.global [%0], [%1], 16, %2;\n"
                 :: "r"(s), "l"(g), "r"(nbytes));
}
__device__ __forceinline__ void ldsm4(uint32_t* r, uint32_t a) {
    asm volatile("ldmatrix.sync.aligned.m8n8.x4.shared.b16 {%0,%1,%2,%3}, [%4];"
                 : "=r"(r[0]), "=r"(r[1]), "=r"(r[2]), "=r"(r[3]) : "r"(a));
}
__device__ __forceinline__ void mma_bf16(float* d, const uint32_t* a,
                                         uint32_t b0, uint32_t b1) {
    asm volatile(
        "mma.sync.aligned.m16n8k16.row.col.f32.bf16.bf16.f32 "
        "{%0,%1,%2,%3}, {%4,%5,%6,%7}, {%8,%9}, {%0,%1,%2,%3};"
        : "+f"(d[0]), "+f"(d[1]), "+f"(d[2]), "+f"(d[3])
        : "r"(a[0]), "r"(a[1]), "r"(a[2]), "r"(a[3]), "r"(b0), "r"(b1));
}
__device__ __forceinline__ uint32_t pack_bf16(float lo, float hi) {
    __nv_bfloat162 p = __floats2bfloat162_rn(lo, hi);
    return *reinterpret_cast<uint32_t*>(&p);
}

// ---------------------------------------------------------------------------
// BF16 tensor-core GEMM body:  C(M,N) = A(M,K=1024) @ W(N,K=1024)^T + bias(N)
// Block 128x128x32, 256 threads / 8 warps (each warp 32x64), 4-stage cp.async
// with wait_group 2 (prefetch distance ~2 iterations of latency cover).
// Fragments via ldmatrix.x4; 80B smem row stride (16B-aligned, conflict-free).
// Runtime out dtype (fp32 / packed bf16); split-bias for fused GEMMs.
// gemm_dual runs two independent GEMM descriptors in ONE launch to kill
// wave-quantization idle (CTA < n0 -> d0, else d1).
// ---------------------------------------------------------------------------
#define RSTR 80              // bytes per smem row
#define STGB (128 * RSTR)    // bytes per matrix per stage (10240)
#define NSTAGE 4

struct GDesc {
    const bf16* A; const bf16* W;
    const float* b1; const float* b2;
    int split; void* C; int N; int gx; int obf;   // obf: 1 -> bf16 out
};

__device__ __forceinline__ void gemm_body(const GDesc d, int bx, int by)
{
    extern __shared__ char smraw[];
    uint32_t abase = smem_u32(smraw);
    uint32_t bbase = abase + NSTAGE * STGB;

    const int K = 1024, NIT = 32;
    int tid = threadIdx.x, wid = tid >> 5, lane = tid & 31;
    int wm = wid & 3, wn = wid >> 2;          // warp tile: rows wm*32, cols wn*64
    int bm = by * 128, bn = bx * 128;
    int N = d.N;

    float acc[2][8][4];
    #pragma unroll
    for (int mt = 0; mt < 2; mt++)
        #pragma unroll
        for (int nt = 0; nt < 8; nt++)
            #pragma unroll
            for (int i = 0; i < 4; i++) acc[mt][nt][i] = 0.f;

    int rowC = tid >> 2, jc = tid & 3;   // 256 threads: 64 rows x 4 chunks / pass

    auto load_stage = [&](int s, int it) {
        int k0 = it * 32;                // bf16 element offset in K
        #pragma unroll
        for (int i = 0; i < 2; ++i) {
            int row = rowC + i * 64;
            cp16(abase + s * STGB + row * RSTR + jc * 16,
                 d.A + (size_t)(bm + row) * K + k0 + jc * 8);
            int srow = bn + row;
            const bf16* src = d.W + (size_t)(srow < N ? srow : 0) * K + k0 + jc * 8;
            cp16p(bbase + s * STGB + row * RSTR + jc * 16,
                  src, srow < N ? 16u : 0u);
        }
        asm volatile("cp.async.commit_group;" ::: "memory");
    };

    // Per-thread ldmatrix row addresses.
    int rA = lane & 15, hA = lane >> 4;
    uint32_t aAddr = abase + (uint32_t)(wm * 32 + rA) * RSTR + hA * 16;
    int rB = (lane & 7) | ((lane >> 4) << 3);
    int hB = (lane >> 3) & 1;
    uint32_t bAddr = bbase + (uint32_t)(wn * 64 + rB) * RSTR + hB * 16;

    load_stage(0, 0);
    load_stage(1, 1);
    load_stage(2, 2);

    int s = 0, pf = 3;
    for (int it = 0; it < NIT; ++it) {
        asm volatile("cp.async.wait_group 2;" ::: "memory");
        __syncthreads();
        if (it + 3 < NIT) {
            load_stage(pf, it + 3);
            pf = (pf == NSTAGE - 1) ? 0 : pf + 1;
        }

        uint32_t ao = aAddr + s * STGB;
        uint32_t bo = bAddr + s * STGB;
        #pragma unroll
        for (int ks = 0; ks < 2; ks++) {          // two k16 steps per BK=32
            uint32_t af[2][4];
            #pragma unroll
            for (int mt = 0; mt < 2; mt++)
                ldsm4(af[mt], ao + mt * (16 * RSTR) + ks * 32);
            #pragma unroll
            for (int nb = 0; nb < 4; nb++) {
                uint32_t bb4[4];
                ldsm4(bb4, bo + nb * (16 * RSTR) + ks * 32);
                #pragma unroll
                for (int mt = 0; mt < 2; mt++) {
                    mma_bf16(acc[mt][2 * nb],     af[mt], bb4[0], bb4[1]);
                    mma_bf16(acc[mt][2 * nb + 1], af[mt], bb4[2], bb4[3]);
                }
            }
        }
        s = (s == NSTAGE - 1) ? 0 : s + 1;
    }

    // Epilogue (split-bias; runtime out dtype)
    int g = lane >> 2, c = lane & 3;
    #pragma unroll
    for (int mt = 0; mt < 2; mt++) {
        int r0 = bm + wm * 32 + mt * 16 + g;
        #pragma unroll
        for (int nt = 0; nt < 8; nt++) {
            int colb = bn + wn * 64 + nt * 8;
            if (colb < N) {
                int cg = colb + 2 * c;
                const float* bp = (colb < d.split) ? (d.b1 + cg) : (d.b2 + cg - d.split);
                float2 bv = *(const float2*)bp;
                float v00 = acc[mt][nt][0] + bv.x, v01 = acc[mt][nt][1] + bv.y;
                float v10 = acc[mt][nt][2] + bv.x, v11 = acc[mt][nt][3] + bv.y;
                if (d.obf) {
                    *(uint32_t*)((bf16*)d.C + (size_t)r0 * N + cg) = pack_bf16(v00, v01);
                    *(uint32_t*)((bf16*)d.C + (size_t)(r0 + 8) * N + cg) = pack_bf16(v10, v11);
                } else {
                    *(float2*)((float*)d.C + (size_t)r0 * N + cg) = make_float2(v00, v01);
                    *(float2*)((float*)d.C + (size_t)(r0 + 8) * N + cg) = make_float2(v10, v11);
                }
            }
        }
    }
}

__global__ void __launch_bounds__(256, 2) gemm_dual(GDesc d0, GDesc d1, int n0)
{
    int cta = blockIdx.x;
    if (cta < n0) {
        gemm_body(d0, cta % d0.gx, cta / d0.gx);
    } else {
        int idx = cta - n0;
        gemm_body(d1, idx % d1.gx, idx / d1.gx);
    }
}

// ---------------------------------------------------------------------------
// LayerNorm (one block per 1024-float row). fp32 in -> bf16 out.
// ---------------------------------------------------------------------------
__global__ void __launch_bounds__(256) ln_kernel(
    const float* __restrict__ in, const float* __restrict__ g,
    const float* __restrict__ b, bf16* __restrict__ out)
{
    __shared__ float red[16];
    int r = blockIdx.x;
    const float4* x4 = (const float4*)(in + (size_t)r * D_);

    int t = threadIdx.x;
    float4 v = x4[t];
    float s  = v.x + v.y + v.z + v.w;
    float ss = v.x * v.x + v.y * v.y + v.z * v.z + v.w * v.w;
    #pragma unroll
    for (int o = 16; o; o >>= 1) {
        s  += __shfl_xor_sync(0xFFFFFFFFu, s,  o);
        ss += __shfl_xor_sync(0xFFFFFFFFu, ss, o);
    }
    int warp = t >> 5, lane = t & 31;
    if (lane == 0) { red[warp] = s; red[8 + warp] = ss; }
    __syncthreads();
    if (t == 0) {
        float S = 0.f, SS = 0.f;
        #pragma unroll
        for (int i = 0; i < 8; i++) { S += red[i]; SS += red[8 + i]; }
        red[0] = S; red[8] = SS;
    }
    __syncthreads();
    float mean = red[0] * (1.0f / D_);
    float var  = red[8] * (1.0f / D_) - mean * mean;
    float inv  = rsqrtf(var + 1e-6f);

    float4 gg = ((const float4*)g)[t];
    float4 bv = ((const float4*)b)[t];
    uint2 u;
    u.x = pack_bf16((v.x - mean) * inv * gg.x + bv.x,
                    (v.y - mean) * inv * gg.y + bv.y);
    u.y = pack_bf16((v.z - mean) * inv * gg.z + bv.z,
                    (v.w - mean) * inv * gg.w + bv.w);
    ((uint2*)(out + (size_t)r * D_))[t] = u;
}

// Fused feat-LN: 4 srcs -> concat layout, bf16. grid = 16384.
__global__ void __launch_bounds__(256) ln_feat_kernel(
    const float* __restrict__ s0, const float* __restrict__ s1,
    const float* __restrict__ s2, const float* __restrict__ s3,
    const float* __restrict__ g, const float* __restrict__ b,
    bf16* __restrict__ out)
{
    __shared__ float red[16];
    int l = blockIdx.x >> 12;
    int r = blockIdx.x & 4095;
    const float* in = (l == 0) ? s0 : (l == 1) ? s1 : (l == 2) ? s2 : s3;
    int bb = r >> 10, rr = r & 1023;
    const float4* x4 = (const float4*)(in + (size_t)r * D_);
    bf16* orow = out + ((size_t)bb * 4096 + l * 1024 + rr) * D_;

    int t = threadIdx.x;
    float4 v = x4[t];
    float s  = v.x + v.y + v.z + v.w;
    float ss = v.x * v.x + v.y * v.y + v.z * v.z + v.w * v.w;
    #pragma unroll
    for (int o = 16; o; o >>= 1) {
        s  += __shfl_xor_sync(0xFFFFFFFFu, s,  o);
        ss += __shfl_xor_sync(0xFFFFFFFFu, ss, o);
    }
    int warp = t >> 5, lane = t & 31;
    if (lane == 0) { red[warp] = s; red[8 + warp] = ss; }
    __syncthreads();
    if (t == 0) {
        float S = 0.f, SS = 0.f;
        #pragma unroll
        for (int i = 0; i < 8; i++) { S += red[i]; SS += red[8 + i]; }
        red[0] = S; red[8] = SS;
    }
    __syncthreads();
    float mean = red[0] * (1.0f / D_);
    float var  = red[8] * (1.0f / D_) - mean * mean;
    float inv  = rsqrtf(var + 1e-6f);

    float4 gg = ((const float4*)g)[t];
    float4 bv = ((const float4*)b)[t];
    uint2 u;
    u.x = pack_bf16((v.x - mean) * inv * gg.x + bv.x,
                    (v.y - mean) * inv * gg.y + bv.y);
    u.y = pack_bf16((v.z - mean) * inv * gg.z + bv.z,
                    (v.w - mean) * inv * gg.w + bv.w);
    ((uint2*)orow)[t] = u;
}

// ---------------------------------------------------------------------------
// Convert all 8 weight matrices to bf16 into g_wrb (single launch).
// ---------------------------------------------------------------------------
struct WPtrs { const float4 *p0,*p1,*p2,*p3,*p4,*p5,*p6,*p7; };

__global__ void round_weights(WPtrs w, bf16* __restrict__ dst)
{
    int i = blockIdx.x * blockDim.x + threadIdx.x;   // float4 index
    if (i >= WTOT / 4) return;
    const float4* src; int base;
    if      (i < WOFF_CAOW/4) { src = w.p0; base = 0; }
    else if (i < WOFF_CAAW/4) { src = w.p1; base = WOFF_CAOW/4; }
    else if (i < WOFF_CAPW/4) { src = w.p2; base = WOFF_CAAW/4; }
    else if (i < WOFF_SAVW/4) { src = w.p3; base = WOFF_CAPW/4; }
    else if (i < WOFF_SAOW/4) { src = w.p4; base = WOFF_SAVW/4; }
    else if (i < WOFF_SAAW/4) { src = w.p5; base = WOFF_SAOW/4; }
    else if (i < WOFF_SAPW/4) { src = w.p6; base = WOFF_SAAW/4; }
    else                      { src = w.p7; base = WOFF_SAPW/4; }
    float4 v = src[i - base];
    uint2 u;
    u.x = pack_bf16(v.x, v.y);
    u.y = pack_bf16(v.z, v.w);
    ((uint2*)dst)[i] = u;
}

// ---------------------------------------------------------------------------
// Softmax over P entries per (b,q,h) inside a combined off+aw row.
// ---------------------------------------------------------------------------
__global__ void softmax_kernel(float* __restrict__ comb, int rstride, int aoff,
                               int P, int total)
{
    int i = blockIdx.x * blockDim.x + threadIdx.x;
    if (i >= total) return;
    float* p = comb + (size_t)(i >> 4) * rstride + aoff + (i & 15) * P;
    float m = -1e30f;
    for (int j = 0; j < P; j++) m = fmaxf(m, p[j]);
    float s = 0.f;
    for (int j = 0; j < P; j++) { float e = __expf(p[j] - m); p[j] = e; s += e; }
    float inv = 1.0f / s;
    for (int j = 0; j < P; j++) p[j] *= inv;
}

// ---------------------------------------------------------------------------
// Deformable sampling: 1 block per (b,q), 16 warps = heads.
// value is bf16: each corner = one 128B line per warp (lane reads 2 bf16).
// Output bf16 (feeds the projection GEMM).
// ---------------------------------------------------------------------------
template<int NL>
__global__ void __launch_bounds__(512) deform_sample(
    const bf16* __restrict__ value, const float* __restrict__ comb,
    int rstride, int aoff, bf16* __restrict__ out)
{
    int bq = blockIdx.x;
    int b = bq >> 10, q = bq & 1023;
    int h = threadIdx.x >> 5, lane = threadIdx.x & 31;

    float rx = ((q & 31) + 0.5f) * 0.03125f;
    float ry = ((q >> 5) + 0.5f) * 0.03125f;

    const float* offp = comb + (size_t)bq * rstride + h * (NL * NP_ * 2);
    const float* awp  = comb + (size_t)bq * rstride + aoff + h * (NL * NP_);
    const bf16* vbase = value + (size_t)b * (NL * 1024) * D_ + h * DH_;

    float2 acc = make_float2(0.f, 0.f);

    #pragma unroll
    for (int l = 0; l < NL; l++) {
        #pragma unroll
        for (int p = 0; p < NP_; p++) {
            int s = l * NP_ + p;
            float ox = offp[s * 2 + 0];
            float oy = offp[s * 2 + 1];
            float a  = awp[s];
            float x = (rx + ox * 0.03125f) * 32.0f - 0.5f;
            float y = (ry + oy * 0.03125f) * 32.0f - 0.5f;
            float x0f = floorf(x), y0f = floorf(y);
            float wx1 = x - x0f, wy1 = y - y0f;
            int x0 = (int)x0f, y0 = (int)y0f;
            #pragma unroll
            for (int dy = 0; dy < 2; dy++) {
                int yi = y0 + dy;
                if ((unsigned)yi >= 32u) continue;
                float wy = dy ? wy1 : (1.0f - wy1);
                #pragma unroll
                for (int dx = 0; dx < 2; dx++) {
                    int xi = x0 + dx;
                    if ((unsigned)xi >= 32u) continue;
                    float w = (dx ? wx1 : (1.0f - wx1)) * wy * a;
                    const uint32_t* vp = (const uint32_t*)(vbase +
                        ((size_t)l * 1024 + yi * 32 + xi) * D_);
                    uint32_t pv = vp[lane];
                    float2 v = __bfloat1622float2(*reinterpret_cast<__nv_bfloat162*>(&pv));
                    acc.x += v.x * w;
                    acc.y += v.y * w;
                }
            }
        }
    }
    uint32_t pv = pack_bf16(acc.x, acc.y);
    ((uint32_t*)(out + (size_t)bq * D_ + h * DH_))[lane] = pv;
}

// ---------------------------------------------------------------------------
// Final residual combine: out = src3 + g1*(attn + g2*attn2)
// ---------------------------------------------------------------------------
__global__ void final_kernel(
    const float* __restrict__ src3, const float* __restrict__ attn,
    const float* __restrict__ attn2, const float* __restrict__ g1,
    const float* __restrict__ g2, float* __restrict__ out, int n4)
{
    int i = blockIdx.x * blockDim.x + threadIdx.x;
    if (i >= n4) return;
    int d4 = i & (D_ / 4 - 1);
    float4 s = ((const float4*)src3)[i];
    float4 a = ((const float4*)attn)[i];
    float4 a2 = ((const float4*)attn2)[i];
    float4 G1 = ((const float4*)g1)[d4];
    float4 G2 = ((const float4*)g2)[d4];
    float4 o;
    o.x = s.x + G1.x * (a.x + G2.x * a2.x);
    o.y = s.y + G1.y * (a.y + G2.y * a2.y);
    o.z = s.z + G1.z * (a.z + G2.z * a2.z);
    o.w = s.w + G1.w * (a.w + G2.w * a2.w);
    ((float4*)out)[i] = o;
}

// ---------------------------------------------------------------------------
// Host launcher
// ---------------------------------------------------------------------------
extern "C" void kernel_launch(void* const* d_in, const int* in_sizes, int n_in,
                              void* d_out, int out_size)
{
    const float* src[4] = {(const float*)d_in[0], (const float*)d_in[1],
                           (const float*)d_in[2], (const float*)d_in[3]};
    const float* qn_g = (const float*)d_in[4];
    const float* qn_b = (const float*)d_in[5];
    const float* fn_g = (const float*)d_in[6];
    const float* fn_b = (const float*)d_in[7];
    const float* n1_g = (const float*)d_in[8];
    const float* n1_b = (const float*)d_in[9];
    const float* gamma1 = (const float*)d_in[10];
    const float* gamma2 = (const float*)d_in[11];
    const float* ca_vb = (const float*)d_in[13];
    const float* ca_ob = (const float*)d_in[15];
    const float* ca_ab = (const float*)d_in[17];
    const float* ca_pb = (const float*)d_in[19];
    const float* sa_vb = (const float*)d_in[21];
    const float* sa_ob = (const float*)d_in[23];
    const float* sa_ab = (const float*)d_in[25];
    const float* sa_pb = (const float*)d_in[27];

    bf16 *fn, *qn, *val, *samp, *attn1, *val2, *samp2, *wr;
    float *offaw, *attn, *offaw2, *attn2;
    cudaGetSymbolAddress((void**)&fn,     g_fn);
    cudaGetSymbolAddress((void**)&qn,     g_qn);
    cudaGetSymbolAddress((void**)&val,    g_val);
    cudaGetSymbolAddress((void**)&offaw,  g_offaw);
    cudaGetSymbolAddress((void**)&samp,   g_samp);
    cudaGetSymbolAddress((void**)&attn,   g_attn);
    cudaGetSymbolAddress((void**)&attn1,  g_attn1);
    cudaGetSymbolAddress((void**)&val2,   g_val2);
    cudaGetSymbolAddress((void**)&offaw2, g_offaw2);
    cudaGetSymbolAddress((void**)&samp2,  g_samp2);
    cudaGetSymbolAddress((void**)&attn2,  g_attn2);
    cudaGetSymbolAddress((void**)&wr,     g_wrb);

    const int ROWS = B_ * LQ_;                    // 4096
    const int SMEM = 2 * NSTAGE * STGB;           // 81920 bytes

    cudaFuncSetAttribute(gemm_dual, cudaFuncAttributeMaxDynamicSharedMemorySize, SMEM);

    WPtrs wp = { (const float4*)d_in[12], (const float4*)d_in[14],
                 (const float4*)d_in[16], (const float4*)d_in[18],
                 (const float4*)d_in[20], (const float4*)d_in[22],
                 (const float4*)d_in[24], (const float4*)d_in[26] };

    // Descriptors
    GDesc dCAoffaw = { qn,    wr + WOFF_CAOW, ca_ob, ca_ab, 512,  offaw,  768,  6, 0 };
    GDesc dCAval   = { fn,    wr + WOFF_CAVW, ca_vb, ca_vb, 1024, val,    1024, 8, 1 };
    GDesc dCAproj  = { samp,  wr + WOFF_CAPW, ca_pb, ca_pb, 1024, attn,   1024, 8, 0 };
    GDesc dSAval   = { attn1, wr + WOFF_SAVW, sa_vb, sa_vb, 1024, val2,   1024, 8, 1 };
    GDesc dSAoffaw = { attn1, wr + WOFF_SAOW, sa_ob, sa_ab, 128,  offaw2, 192,  2, 0 };
    GDesc dSAproj  = { samp2, wr + WOFF_SAPW, sa_pb, sa_pb, 1024, attn2,  1024, 8, 0 };

    // 1-3) LayerNorms + weight conversion (all bf16 outputs)
    ln_feat_kernel<<<4 * ROWS, 256>>>(src[0], src[1], src[2], src[3], fn_g, fn_b, fn);
    ln_kernel<<<ROWS, 256>>>(src[3], qn_g, qn_b, qn);
    round_weights<<<(WTOT / 4 + 255) / 256, 256>>>(wp, wr);
    // 4) Combined CA GEMMs: off+aw (192 CTAs) || value (1024 CTAs)
    gemm_dual<<<192 + 1024, 256, SMEM>>>(dCAoffaw, dCAval, 192);
    // 5) softmax on aw part
    softmax_kernel<<<(ROWS * NH_ + 255) / 256, 256>>>(offaw, 768, 512, 16, ROWS * NH_);
    // 6) CA sampler (the launch ncu -s 5 -c 1 captures)
    deform_sample<4><<<ROWS, 512>>>(val, offaw, 768, 512, samp);
    // 7) CA projection
    gemm_dual<<<256, 256, SMEM>>>(dCAproj, dCAproj, 256);
    // 8-12) SA branch
    ln_kernel<<<ROWS, 256>>>(attn, n1_g, n1_b, attn1);
    gemm_dual<<<256 + 64, 256, SMEM>>>(dSAval, dSAoffaw, 256);
    softmax_kernel<<<(ROWS * NH_ + 255) / 256, 256>>>(offaw2, 192, 128, 4, ROWS * NH_);
    deform_sample<1><<<ROWS, 512>>>(val2, offaw2, 192, 128, samp2);
    gemm_dual<<<256, 256, SMEM>>>(dSAproj, dSAproj, 256);
    // 13) Final combine
    final_kernel<<<(ROWS * D_ / 4 + 255) / 256, 256>>>(
        src[3], attn, attn2, gamma1, gamma2, (float*)d_out, ROWS * D_ / 4);
}